// round 2
// baseline (speedup 1.0000x reference)
#include <cuda_runtime.h>
#include <math.h>

#define B_  32
#define NH  778
#define NO  3000
#define Z_  64
#define NPRIOR 204

// obj path: queries = obj points (3000/batch), targets = recon & gt hands (778)
#define OBJ_TILE    200      // targets per shared tile (4 tiles -> 800 slots)
#define OBJ_TILES   4
#define OBJ_CHUNKS  12       // 12 * 256 query-slots = 3072 >= 3000
// hand path: queries = hand points (778/batch), targets = obj points (3000)
#define HAND_TILE   128      // 24 tiles -> 3072 slots
#define HAND_TILES  24
#define HAND_CHUNKS 4        // 4 * 256 query-slots = 1024 >= 778

#define OBJ_BLOCKS   (OBJ_CHUNKS * B_)    // 384
#define HAND_BLOCKS  (HAND_CHUNKS * B_)   // 128
#define TOTAL_BLOCKS (OBJ_BLOCKS + HAND_BLOCKS)

// Accumulators:
// 0: recon MSE   1: kld   2: penetr   3: n_pts
// 4: contact     5: consist   6: loss_o sum   7: loss_h sum
__device__ double g_acc[8];
__device__ unsigned g_maskbits[NH];   // 0 if prior vertex, 0xFFFFFFFF otherwise

__constant__ int c_prior[NPRIOR] = {
  697,698,699,700,712,713,714,715,737,738,739,740,741,743,744,745,
  746,748,749,750,753,754,755,756,757,758,759,760,761,762,763,764,
  765,766,767,768,
  46,47,48,49,164,165,166,167,194,195,223,237,238,280,281,298,
  301,317,320,323,324,325,326,327,328,329,330,331,332,333,340,341,
  342,343,344,345,346,347,348,349,350,351,352,353,354,355,
  356,357,358,359,375,376,386,387,396,397,402,403,413,429,433,434,
  435,436,437,438,439,440,441,442,443,444,452,453,454,455,456,459,
  460,461,462,463,464,465,466,467,
  468,469,470,471,484,485,486,496,497,506,507,513,514,524,545,546,
  547,548,549,550,551,552,553,555,563,564,565,566,567,570,572,573,
  574,575,576,577,578,
  580,581,582,583,600,601,602,614,615,624,625,630,631,641,663,664,
  665,666,667,668,670,672,680,681,682,683,684,686,687,688,689,690,
  691,692,693,694,695,
  73,96,98,99,772,774,775,777
};

__global__ void k_init() {
    int t = threadIdx.x;
    if (t < 8) g_acc[t] = 0.0;
    for (int i = t; i < NH; i += blockDim.x) g_maskbits[i] = 0xFFFFFFFFu;
    __syncthreads();
    if (t < NPRIOR) g_maskbits[c_prior[t]] = 0u;
}

__device__ __forceinline__ float warp_sum(float v) {
#pragma unroll
    for (int o = 16; o > 0; o >>= 1) v += __shfl_down_sync(0xffffffffu, v, o);
    return v;
}

__device__ __forceinline__ float sgnf(float x) {
    return (x > 0.f) ? 1.f : ((x < 0.f) ? -1.f : 0.f);
}

struct ObjSmem {
    float4   r[OBJ_TILE];
    float4   g[OBJ_TILE];
    unsigned f[OBJ_TILE];
};

union SmemU {
    ObjSmem o;
    float4  h[HAND_TILE];
};

__global__ void __launch_bounds__(128) k_main(
    const float* __restrict__ recon, const float* __restrict__ gt,
    const float* __restrict__ recon_n, const float* __restrict__ gt_n,
    const float* __restrict__ obj, const float* __restrict__ vw)
{
    __shared__ __align__(16) SmemU S;
    __shared__ float red[4][5];
    const int tid = threadIdx.x;
    const int lane = tid & 31, warp = tid >> 5;

    if (blockIdx.x < OBJ_BLOCKS) {
        // ===================== OBJ path =====================
        const int b     = blockIdx.x / OBJ_CHUNKS;
        const int chunk = blockIdx.x % OBJ_CHUNKS;
        const int j0 = chunk * 256 + tid;
        const int j1 = j0 + 128;
        const bool a0 = (j0 < NO), a1 = (j1 < NO);
        const int jj0 = a0 ? j0 : (NO - 1);
        const int jj1 = a1 ? j1 : (NO - 1);

        const float* ob = obj + (size_t)b * NO * 3;
        const float ox0 = ob[3*jj0], oy0 = ob[3*jj0+1], oz0 = ob[3*jj0+2];
        const float ox1 = ob[3*jj1], oy1 = ob[3*jj1+1], oz1 = ob[3*jj1+2];
        const float b0 = 0.5f*(ox0*ox0 + oy0*oy0 + oz0*oz0);
        const float b1 = 0.5f*(ox1*ox1 + oy1*oy1 + oz1*oz1);
        const float nx0 = -ox0, ny0 = -oy0, nz0 = -oz0;
        const float nx1 = -ox1, ny1 = -oy1, nz1 = -oz1;

        unsigned br0 = 0xFFFFFFFFu, br1 = 0xFFFFFFFFu;
        unsigned bp0 = 0xFFFFFFFFu, bp1 = 0xFFFFFFFFu;
        unsigned bg0 = 0xFFFFFFFFu, bg1 = 0xFFFFFFFFu;

        const float* rb = recon + (size_t)b * NH * 3;
        const float* gb = gt    + (size_t)b * NH * 3;

        for (int t = 0; t < OBJ_TILES; t++) {
            const int t0 = t * OBJ_TILE;
            __syncthreads();
            for (int k = tid; k < OBJ_TILE; k += 128) {
                const int tg = t0 + k;
                if (tg < NH) {
                    float x = rb[3*tg], y = rb[3*tg+1], z = rb[3*tg+2];
                    S.o.r[k] = make_float4(x, y, z, 0.5f*(x*x + y*y + z*z));
                    x = gb[3*tg]; y = gb[3*tg+1]; z = gb[3*tg+2];
                    S.o.g[k] = make_float4(x, y, z, 0.5f*(x*x + y*y + z*z));
                    S.o.f[k] = g_maskbits[tg];
                } else {
                    S.o.r[k] = make_float4(0.f, 0.f, 0.f, __int_as_float(0x7F800000));
                    S.o.g[k] = make_float4(0.f, 0.f, 0.f, __int_as_float(0x7F800000));
                    S.o.f[k] = 0xFFFFFFFFu;
                }
            }
            __syncthreads();
#pragma unroll 4
            for (int k = 0; k < OBJ_TILE; k++) {
                const float4 r = S.o.r[k];
                const float4 g = S.o.g[k];
                const unsigned fl = S.o.f[k];
                const unsigned kb = (unsigned)(t0 + k);
                // q0 vs recon
                float m = b0 + r.w;
                m = fmaf(nx0, r.x, m); m = fmaf(ny0, r.y, m); m = fmaf(nz0, r.z, m);
                unsigned key = (__float_as_uint(m) & 0xFFFFFC00u) | kb;
                br0 = min(br0, key);
                bp0 = min(bp0, key | fl);
                // q1 vs recon
                m = b1 + r.w;
                m = fmaf(nx1, r.x, m); m = fmaf(ny1, r.y, m); m = fmaf(nz1, r.z, m);
                key = (__float_as_uint(m) & 0xFFFFFC00u) | kb;
                br1 = min(br1, key);
                bp1 = min(bp1, key | fl);
                // q0 vs gt
                m = b0 + g.w;
                m = fmaf(nx0, g.x, m); m = fmaf(ny0, g.y, m); m = fmaf(nz0, g.z, m);
                key = (__float_as_uint(m) & 0xFFFFFC00u) | kb;
                bg0 = min(bg0, key);
                // q1 vs gt
                m = b1 + g.w;
                m = fmaf(nx1, g.x, m); m = fmaf(ny1, g.y, m); m = fmaf(nz1, g.z, m);
                key = (__float_as_uint(m) & 0xFFFFFC00u) | kb;
                bg1 = min(bg1, key);
            }
        }

        // epilogue: exact recompute from winning indices
        float vals[5] = {0.f, 0.f, 0.f, 0.f, 0.f};
        const float* rnb = recon_n + (size_t)b * NH * 3;
        const float* gnb = gt_n    + (size_t)b * NH * 3;
#pragma unroll
        for (int q = 0; q < 2; q++) {
            const bool act = q ? a1 : a0;
            if (!act) continue;
            const float ox = q ? ox1 : ox0, oy = q ? oy1 : oy0, oz = q ? oz1 : oz0;
            const int ir = (int)((q ? br1 : br0) & 1023u);
            const int ig = (int)((q ? bg1 : bg0) & 1023u);
            const int ip = (int)((q ? bp1 : bp0) & 1023u);

            float dxr = ox - rb[3*ir], dyr = oy - rb[3*ir+1], dzr = oz - rb[3*ir+2];
            float d2r = dxr*dxr + dyr*dyr + dzr*dzr;
            float dotr = rnb[3*ir]*dxr + rnb[3*ir+1]*dyr + rnb[3*ir+2]*dzr;
            float o2h = sqrtf(d2r) * sgnf(dotr);
            bool interior = (-dotr) > 0.f;

            float dxg = ox - gb[3*ig], dyg = oy - gb[3*ig+1], dzg = oz - gb[3*ig+2];
            float d2g = dxg*dxg + dyg*dyg + dzg*dzg;
            float dotg = gnb[3*ig]*dxg + gnb[3*ig+1]*dyg + gnb[3*ig+2]*dzg;
            float o2h_gt = sqrtf(d2g) * sgnf(dotg);

            float dxp = ox - rb[3*ip], dyp = oy - rb[3*ip+1], dzp = oz - rb[3*ip+2];
            float d2p = dxp*dxp + dyp*dyp + dzp*dzp;

            bool cmap  = sqrtf(d2g) < 0.005f;
            bool rcmap = sqrtf(d2r) < 0.005f;

            vals[0] += interior ? d2r : 0.f;               // penetr
            vals[1] += cmap ? 1.f : 0.f;                   // n_pts
            vals[2] += cmap ? d2p : 0.f;                   // contact
            vals[3] += (cmap && rcmap) ? 1.f : 0.f;        // consistency
            bool w_dist = (o2h_gt < 0.01f) && (o2h_gt > -0.005f);
            float w = (o2h < 0.f) ? 1.5f : (w_dist ? 1.0f : 0.1f);
            vals[4] += fabsf(o2h - o2h_gt) * w;            // loss_o
        }

#pragma unroll
        for (int q = 0; q < 5; q++) {
            float v = warp_sum(vals[q]);
            if (lane == 0) red[warp][q] = v;
        }
        __syncthreads();
        if (tid == 0) {
#pragma unroll
            for (int q = 0; q < 5; q++) {
                float s = red[0][q] + red[1][q] + red[2][q] + red[3][q];
                atomicAdd(&g_acc[2 + q], (double)s);
            }
        }
    } else {
        // ===================== HAND path =====================
        const int hb    = blockIdx.x - OBJ_BLOCKS;
        const int b     = hb / HAND_CHUNKS;
        const int chunk = hb % HAND_CHUNKS;
        const int i0 = chunk * 256 + tid;
        const int i1 = i0 + 128;
        const bool a0 = (i0 < NH), a1 = (i1 < NH);
        const int ii0 = a0 ? i0 : (NH - 1);
        const int ii1 = a1 ? i1 : (NH - 1);

        const float* rb = recon + (size_t)b * NH * 3;
        const float* gb = gt    + (size_t)b * NH * 3;
        const float rx0 = rb[3*ii0], ry0 = rb[3*ii0+1], rz0 = rb[3*ii0+2];
        const float gx0 = gb[3*ii0], gy0 = gb[3*ii0+1], gz0 = gb[3*ii0+2];
        const float rx1 = rb[3*ii1], ry1 = rb[3*ii1+1], rz1 = rb[3*ii1+2];
        const float gx1 = gb[3*ii1], gy1 = gb[3*ii1+1], gz1 = gb[3*ii1+2];
        const float br_ = 0.5f*(rx0*rx0+ry0*ry0+rz0*rz0);
        const float bg_ = 0.5f*(gx0*gx0+gy0*gy0+gz0*gz0);
        const float br2 = 0.5f*(rx1*rx1+ry1*ry1+rz1*rz1);
        const float bg2 = 0.5f*(gx1*gx1+gy1*gy1+gz1*gz1);
        const float nrx0=-rx0, nry0=-ry0, nrz0=-rz0, ngx0=-gx0, ngy0=-gy0, ngz0=-gz0;
        const float nrx1=-rx1, nry1=-ry1, nrz1=-rz1, ngx1=-gx1, ngy1=-gy1, ngz1=-gz1;

        unsigned kr0 = 0xFFFFFFFFu, kg0 = 0xFFFFFFFFu;
        unsigned kr1 = 0xFFFFFFFFu, kg1 = 0xFFFFFFFFu;

        const float* obp = obj + (size_t)b * NO * 3;

        for (int t = 0; t < HAND_TILES; t++) {
            const int t0 = t * HAND_TILE;
            __syncthreads();
            {
                const int tg = t0 + tid;
                if (tg < NO) {
                    float x = obp[3*tg], y = obp[3*tg+1], z = obp[3*tg+2];
                    S.h[tid] = make_float4(x, y, z, 0.5f*(x*x + y*y + z*z));
                } else {
                    S.h[tid] = make_float4(0.f, 0.f, 0.f, __int_as_float(0x7F800000));
                }
            }
            __syncthreads();
#pragma unroll 4
            for (int k = 0; k < HAND_TILE; k++) {
                const float4 o = S.h[k];
                const unsigned kb = (unsigned)(t0 + k);
                float m = br_ + o.w;
                m = fmaf(nrx0, o.x, m); m = fmaf(nry0, o.y, m); m = fmaf(nrz0, o.z, m);
                kr0 = min(kr0, (__float_as_uint(m) & 0xFFFFF000u) | kb);
                m = bg_ + o.w;
                m = fmaf(ngx0, o.x, m); m = fmaf(ngy0, o.y, m); m = fmaf(ngz0, o.z, m);
                kg0 = min(kg0, (__float_as_uint(m) & 0xFFFFF000u) | kb);
                m = br2 + o.w;
                m = fmaf(nrx1, o.x, m); m = fmaf(nry1, o.y, m); m = fmaf(nrz1, o.z, m);
                kr1 = min(kr1, (__float_as_uint(m) & 0xFFFFF000u) | kb);
                m = bg2 + o.w;
                m = fmaf(ngx1, o.x, m); m = fmaf(ngy1, o.y, m); m = fmaf(ngz1, o.z, m);
                kg1 = min(kg1, (__float_as_uint(m) & 0xFFFFF000u) | kb);
            }
        }

        float c = 0.f;
        if (a0) {
            const int ir = (int)(kr0 & 4095u), ig = (int)(kg0 & 4095u);
            float dx = rx0 - obp[3*ir], dy = ry0 - obp[3*ir+1], dz = rz0 - obp[3*ir+2];
            float h2o = sqrtf(dx*dx + dy*dy + dz*dz);
            dx = gx0 - obp[3*ig]; dy = gy0 - obp[3*ig+1]; dz = gz0 - obp[3*ig+2];
            float h2o_gt = sqrtf(dx*dx + dy*dy + dz*dz);
            c += fabsf(h2o - h2o_gt) * powf(vw[i0], 0.4f);
        }
        if (a1) {
            const int ir = (int)(kr1 & 4095u), ig = (int)(kg1 & 4095u);
            float dx = rx1 - obp[3*ir], dy = ry1 - obp[3*ir+1], dz = rz1 - obp[3*ir+2];
            float h2o = sqrtf(dx*dx + dy*dy + dz*dz);
            dx = gx1 - obp[3*ig]; dy = gy1 - obp[3*ig+1]; dz = gz1 - obp[3*ig+2];
            float h2o_gt = sqrtf(dx*dx + dy*dy + dz*dz);
            c += fabsf(h2o - h2o_gt) * powf(vw[i1], 0.4f);
        }

        float v = warp_sum(c);
        if (lane == 0) red[warp][0] = v;
        __syncthreads();
        if (tid == 0) {
            float s = red[0][0] + red[1][0] + red[2][0] + red[3][0];
            atomicAdd(&g_acc[7], (double)s);
        }
    }
}

__global__ void k_small(
    const float* __restrict__ recon, const float* __restrict__ gt,
    const float* __restrict__ mean, const float* __restrict__ logv)
{
    const int NREC = B_ * NH * 3;
    const int NKLD = B_ * Z_;
    float s_rec = 0.f, s_kld = 0.f;
    int stride = gridDim.x * blockDim.x;
    for (int i = blockIdx.x * blockDim.x + threadIdx.x; i < NREC; i += stride) {
        float d = recon[i] - gt[i];
        s_rec += d * d;
    }
    for (int i = blockIdx.x * blockDim.x + threadIdx.x; i < NKLD; i += stride) {
        float m = mean[i], lv = logv[i];
        s_kld += 1.f + lv - m * m - expf(lv);
    }
    __shared__ float red[8][2];
    int lane = threadIdx.x & 31, warp = threadIdx.x >> 5;
    float v0 = warp_sum(s_rec), v1 = warp_sum(s_kld);
    if (lane == 0) { red[warp][0] = v0; red[warp][1] = v1; }
    __syncthreads();
    if (threadIdx.x == 0) {
        float a = 0.f, b = 0.f;
        for (int wi = 0; wi < 8; wi++) { a += red[wi][0]; b += red[wi][1]; }
        atomicAdd(&g_acc[0], (double)a);
        atomicAdd(&g_acc[1], (double)b);
    }
}

__global__ void k_final(float* out) {
    const double KLC = 0.005;
    double recon_loss = g_acc[0] / B_;
    double kld        = -0.5 * g_acc[1] / B_ * 10.0;
    double penetr     = 100.0 * g_acc[2] / B_;
    double npts       = g_acc[3];
    double contact    = 3000.0 * ((npts > 0.0) ? (g_acc[4] / (B_ * npts)) : 0.0);
    double consist    = -5.0 * g_acc[5] / (npts + 0.0001);
    double loss_o     = 30.0 * (1.0 - KLC) * g_acc[6] / ((double)B_ * NO);
    double loss_h     = 35.0 * (1.0 - KLC) * g_acc[7] / ((double)B_ * NH);
    double total = 1.0 * recon_loss + 0.1 * kld + 1000.0 * penetr
                 + 10.0 * contact + 10.0 * consist + (loss_h + loss_o);
    out[0] = (float)total;
}

extern "C" void kernel_launch(void* const* d_in, const int* in_sizes, int n_in,
                              void* d_out, int out_size) {
    const float* recon   = (const float*)d_in[0];
    const float* gt      = (const float*)d_in[1];
    const float* recon_n = (const float*)d_in[2];
    const float* gt_n    = (const float*)d_in[3];
    const float* obj     = (const float*)d_in[4];
    const float* mean    = (const float*)d_in[5];
    const float* logv    = (const float*)d_in[6];
    const float* vw      = (const float*)d_in[7];
    float* out = (float*)d_out;

    k_init<<<1, 1024>>>();
    k_main<<<TOTAL_BLOCKS, 128>>>(recon, gt, recon_n, gt_n, obj, vw);
    k_small<<<64, 256>>>(recon, gt, mean, logv);
    k_final<<<1, 1>>>(out);
}

// round 3
// speedup vs baseline: 1.5026x; 1.5026x over previous
#include <cuda_runtime.h>
#include <math.h>

#define B_  32
#define NH  778
#define NO  3000
#define Z_  64
#define NPRIOR 204

// obj path: 12 chunks x 32 batches, 256 thr, 1 query/thread
#define OBJ_TILE    200
#define OBJ_TILES   4          // 800 slots >= 778
#define OBJ_CHUNKS  12         // 12*256 = 3072 >= 3000
#define OBJ_BLOCKS  (OBJ_CHUNKS * B_)          // 384
// hand path: 4 qchunks x 3 target-segments x 32 batches
#define HAND_QCH    4          // 4*256 = 1024 >= 778
#define HAND_TSEG   3
#define HAND_SEGLEN 1000
#define HAND_TILE   200        // 5 tiles per segment
#define HAND_BLOCKS (HAND_QCH * HAND_TSEG * B_) // 384
#define TOTAL_BLOCKS (OBJ_BLOCKS + HAND_BLOCKS) // 768

// 0: recon MSE  1: kld  2: penetr  3: n_pts  4: contact  5: consist  6: loss_o  7: loss_h
__device__ double g_acc[8];
__device__ float  g_maskf[NH];            // 0 for prior verts, +INF otherwise
__device__ unsigned g_mhr[B_ * NH];       // hand->obj min m (recon), uint-bits of float
__device__ unsigned g_mhg[B_ * NH];       // hand->obj min m (gt)

__constant__ int c_prior[NPRIOR] = {
  697,698,699,700,712,713,714,715,737,738,739,740,741,743,744,745,
  746,748,749,750,753,754,755,756,757,758,759,760,761,762,763,764,
  765,766,767,768,
  46,47,48,49,164,165,166,167,194,195,223,237,238,280,281,298,
  301,317,320,323,324,325,326,327,328,329,330,331,332,333,340,341,
  342,343,344,345,346,347,348,349,350,351,352,353,354,355,
  356,357,358,359,375,376,386,387,396,397,402,403,413,429,433,434,
  435,436,437,438,439,440,441,442,443,444,452,453,454,455,456,459,
  460,461,462,463,464,465,466,467,
  468,469,470,471,484,485,486,496,497,506,507,513,514,524,545,546,
  547,548,549,550,551,552,553,555,563,564,565,566,567,570,572,573,
  574,575,576,577,578,
  580,581,582,583,600,601,602,614,615,624,625,630,631,641,663,664,
  665,666,667,668,670,672,680,681,682,683,684,686,687,688,689,690,
  691,692,693,694,695,
  73,96,98,99,772,774,775,777
};

__global__ void k_init() {
    const int gid = blockIdx.x * blockDim.x + threadIdx.x;
    const int stride = gridDim.x * blockDim.x;
    for (int i = gid; i < B_ * NH; i += stride) {
        g_mhr[i] = 0x7F800000u;   // +INF
        g_mhg[i] = 0x7F800000u;
    }
    if (blockIdx.x == 0) {
        int t = threadIdx.x;
        if (t < 8) g_acc[t] = 0.0;
        for (int i = t; i < NH; i += blockDim.x)
            g_maskf[i] = __int_as_float(0x7F800000);
        __syncthreads();
        if (t < NPRIOR) g_maskf[c_prior[t]] = 0.f;
    }
}

__device__ __forceinline__ float warp_sum(float v) {
#pragma unroll
    for (int o = 16; o > 0; o >>= 1) v += __shfl_down_sync(0xffffffffu, v, o);
    return v;
}

__device__ __forceinline__ float sgnf(float x) {
    return (x > 0.f) ? 1.f : ((x < 0.f) ? -1.f : 0.f);
}

struct ObjSmem {
    float4 r[OBJ_TILE];
    float4 g[OBJ_TILE];
    float  f[OBJ_TILE];
};
union SmemU {
    ObjSmem o;
    float4  h[HAND_TILE];
};

__global__ void __launch_bounds__(256) k_main(
    const float* __restrict__ recon, const float* __restrict__ gt,
    const float* __restrict__ recon_n, const float* __restrict__ gt_n,
    const float* __restrict__ obj)
{
    __shared__ __align__(16) SmemU S;
    __shared__ float red[8][5];
    const int tid = threadIdx.x;
    const int lane = tid & 31, warp = tid >> 5;
    const float FINF = __int_as_float(0x7F800000);

    if (blockIdx.x < OBJ_BLOCKS) {
        // ===================== OBJ path (argmin vs recon/gt, min vs prior) ====
        const int b     = blockIdx.x / OBJ_CHUNKS;
        const int chunk = blockIdx.x % OBJ_CHUNKS;
        const int j = chunk * 256 + tid;
        const bool act = (j < NO);
        const int jj = act ? j : (NO - 1);

        const float* ob = obj + (size_t)b * NO * 3;
        const float ox = ob[3*jj], oy = ob[3*jj+1], oz = ob[3*jj+2];
        const float bq = 0.5f * (ox*ox + oy*oy + oz*oz);
        const float nx = -ox, ny = -oy, nz = -oz;

        unsigned br = 0xFFFFFFFFu, bg = 0xFFFFFFFFu;
        float mp = FINF;

        const float* rb = recon + (size_t)b * NH * 3;
        const float* gb = gt    + (size_t)b * NH * 3;

        for (int t = 0; t < OBJ_TILES; t++) {
            const int t0 = t * OBJ_TILE;
            __syncthreads();
            if (tid < OBJ_TILE) {
                const int tg = t0 + tid;
                if (tg < NH) {
                    float x = rb[3*tg], y = rb[3*tg+1], z = rb[3*tg+2];
                    S.o.r[tid] = make_float4(x, y, z, 0.5f*(x*x + y*y + z*z));
                    x = gb[3*tg]; y = gb[3*tg+1]; z = gb[3*tg+2];
                    S.o.g[tid] = make_float4(x, y, z, 0.5f*(x*x + y*y + z*z));
                    S.o.f[tid] = g_maskf[tg];
                } else {
                    S.o.r[tid] = make_float4(0.f, 0.f, 0.f, FINF);
                    S.o.g[tid] = make_float4(0.f, 0.f, 0.f, FINF);
                    S.o.f[tid] = FINF;
                }
            }
            __syncthreads();
#pragma unroll 4
            for (int k = 0; k < OBJ_TILE; k++) {
                const float4 r = S.o.r[k];
                const float4 g = S.o.g[k];
                const float fl = S.o.f[k];
                const unsigned kb = (unsigned)(t0 + k);
                float m = bq + r.w;
                m = fmaf(nx, r.x, m); m = fmaf(ny, r.y, m); m = fmaf(nz, r.z, m);
                br = min(br, (__float_as_uint(m) & 0xFFFFFC00u) | kb);
                mp = fminf(mp, m + fl);
                float mg = bq + g.w;
                mg = fmaf(nx, g.x, mg); mg = fmaf(ny, g.y, mg); mg = fmaf(nz, g.z, mg);
                bg = min(bg, (__float_as_uint(mg) & 0xFFFFFC00u) | kb);
            }
        }

        float vals[5] = {0.f, 0.f, 0.f, 0.f, 0.f};
        if (act) {
            const float* rnb = recon_n + (size_t)b * NH * 3;
            const float* gnb = gt_n    + (size_t)b * NH * 3;
            const int ir = (int)(br & 1023u);
            const int ig = (int)(bg & 1023u);

            float dxr = ox - rb[3*ir], dyr = oy - rb[3*ir+1], dzr = oz - rb[3*ir+2];
            float d2r = dxr*dxr + dyr*dyr + dzr*dzr;
            float dotr = rnb[3*ir]*dxr + rnb[3*ir+1]*dyr + rnb[3*ir+2]*dzr;
            float o2h = sqrtf(d2r) * sgnf(dotr);
            bool interior = (-dotr) > 0.f;

            float dxg = ox - gb[3*ig], dyg = oy - gb[3*ig+1], dzg = oz - gb[3*ig+2];
            float d2g = dxg*dxg + dyg*dyg + dzg*dzg;
            float dotg = gnb[3*ig]*dxg + gnb[3*ig+1]*dyg + gnb[3*ig+2]*dzg;
            float o2h_gt = sqrtf(d2g) * sgnf(dotg);

            float d2p = fmaxf(2.f * mp, 0.f);

            bool cmap  = sqrtf(d2g) < 0.005f;
            bool rcmap = sqrtf(d2r) < 0.005f;

            vals[0] = interior ? d2r : 0.f;
            vals[1] = cmap ? 1.f : 0.f;
            vals[2] = cmap ? d2p : 0.f;
            vals[3] = (cmap && rcmap) ? 1.f : 0.f;
            bool w_dist = (o2h_gt < 0.01f) && (o2h_gt > -0.005f);
            float w = (o2h < 0.f) ? 1.5f : (w_dist ? 1.0f : 0.1f);
            vals[4] = fabsf(o2h - o2h_gt) * w;
        }

#pragma unroll
        for (int q = 0; q < 5; q++) {
            float v = warp_sum(vals[q]);
            if (lane == 0) red[warp][q] = v;
        }
        __syncthreads();
        if (tid < 5) {
            float s = 0.f;
            for (int wi = 0; wi < 8; wi++) s += red[wi][tid];
            atomicAdd(&g_acc[2 + tid], (double)s);
        }
    } else {
        // ===================== HAND path (min-distance only, no argmin) =======
        const int hb  = blockIdx.x - OBJ_BLOCKS;
        const int b   = hb / (HAND_QCH * HAND_TSEG);
        const int r_  = hb % (HAND_QCH * HAND_TSEG);
        const int qc  = r_ / HAND_TSEG;
        const int ts  = r_ % HAND_TSEG;
        const int i = qc * 256 + tid;
        const bool act = (i < NH);
        const int ii = act ? i : (NH - 1);

        const float* rb = recon + (size_t)b * NH * 3;
        const float* gb = gt    + (size_t)b * NH * 3;
        const float rx = rb[3*ii], ry = rb[3*ii+1], rz = rb[3*ii+2];
        const float gx = gb[3*ii], gy = gb[3*ii+1], gz = gb[3*ii+2];
        const float brq = 0.5f*(rx*rx + ry*ry + rz*rz);
        const float bgq = 0.5f*(gx*gx + gy*gy + gz*gz);
        const float nrx = -rx, nry = -ry, nrz = -rz;
        const float ngx = -gx, ngy = -gy, ngz = -gz;

        float mr = FINF, mg = FINF;
        const float* obp = obj + (size_t)b * NO * 3 + (size_t)ts * HAND_SEGLEN * 3;

        for (int t = 0; t < HAND_SEGLEN; t += HAND_TILE) {
            __syncthreads();
            if (tid < HAND_TILE) {
                const int tg = t + tid;
                float x = obp[3*tg], y = obp[3*tg+1], z = obp[3*tg+2];
                S.h[tid] = make_float4(x, y, z, 0.5f*(x*x + y*y + z*z));
            }
            __syncthreads();
#pragma unroll 4
            for (int k = 0; k < HAND_TILE; k++) {
                const float4 o = S.h[k];
                float m = brq + o.w;
                m = fmaf(nrx, o.x, m); m = fmaf(nry, o.y, m); m = fmaf(nrz, o.z, m);
                mr = fminf(mr, m);
                m = bgq + o.w;
                m = fmaf(ngx, o.x, m); m = fmaf(ngy, o.y, m); m = fmaf(ngz, o.z, m);
                mg = fminf(mg, m);
            }
        }

        if (act) {
            const int gidx = b * NH + i;
            atomicMin(&g_mhr[gidx], __float_as_uint(fmaxf(mr, 0.f)));
            atomicMin(&g_mhg[gidx], __float_as_uint(fmaxf(mg, 0.f)));
        }
    }
}

// Epilogue: loss_h from merged hand mins + recon MSE + KLD
__global__ void __launch_bounds__(256) k_epi(
    const float* __restrict__ recon, const float* __restrict__ gt,
    const float* __restrict__ mean, const float* __restrict__ logv,
    const float* __restrict__ vw)
{
    const int gid = blockIdx.x * blockDim.x + threadIdx.x;
    const int stride = gridDim.x * blockDim.x;

    float s_h = 0.f, s_rec = 0.f, s_kld = 0.f;
    for (int j = gid; j < B_ * NH; j += stride) {
        const int i = j % NH;
        float dr = sqrtf(fmaxf(2.f * __uint_as_float(g_mhr[j]), 0.f));
        float dg = sqrtf(fmaxf(2.f * __uint_as_float(g_mhg[j]), 0.f));
        s_h += fabsf(dr - dg) * powf(vw[i], 0.4f);
    }
    for (int i = gid; i < B_ * NH * 3; i += stride) {
        float d = recon[i] - gt[i];
        s_rec += d * d;
    }
    for (int i = gid; i < B_ * Z_; i += stride) {
        float m = mean[i], lv = logv[i];
        s_kld += 1.f + lv - m * m - expf(lv);
    }

    __shared__ float red[8][3];
    const int lane = threadIdx.x & 31, warp = threadIdx.x >> 5;
    float v0 = warp_sum(s_h), v1 = warp_sum(s_rec), v2 = warp_sum(s_kld);
    if (lane == 0) { red[warp][0] = v0; red[warp][1] = v1; red[warp][2] = v2; }
    __syncthreads();
    if (threadIdx.x == 0) {
        float a = 0.f, b = 0.f, c = 0.f;
        for (int wi = 0; wi < 8; wi++) { a += red[wi][0]; b += red[wi][1]; c += red[wi][2]; }
        atomicAdd(&g_acc[7], (double)a);
        atomicAdd(&g_acc[0], (double)b);
        atomicAdd(&g_acc[1], (double)c);
    }
}

__global__ void k_final(float* out) {
    const double KLC = 0.005;
    double recon_loss = g_acc[0] / B_;
    double kld        = -0.5 * g_acc[1] / B_ * 10.0;
    double penetr     = 100.0 * g_acc[2] / B_;
    double npts       = g_acc[3];
    double contact    = 3000.0 * ((npts > 0.0) ? (g_acc[4] / (B_ * npts)) : 0.0);
    double consist    = -5.0 * g_acc[5] / (npts + 0.0001);
    double loss_o     = 30.0 * (1.0 - KLC) * g_acc[6] / ((double)B_ * NO);
    double loss_h     = 35.0 * (1.0 - KLC) * g_acc[7] / ((double)B_ * NH);
    double total = 1.0 * recon_loss + 0.1 * kld + 1000.0 * penetr
                 + 10.0 * contact + 10.0 * consist + (loss_h + loss_o);
    out[0] = (float)total;
}

extern "C" void kernel_launch(void* const* d_in, const int* in_sizes, int n_in,
                              void* d_out, int out_size) {
    const float* recon   = (const float*)d_in[0];
    const float* gt      = (const float*)d_in[1];
    const float* recon_n = (const float*)d_in[2];
    const float* gt_n    = (const float*)d_in[3];
    const float* obj     = (const float*)d_in[4];
    const float* mean    = (const float*)d_in[5];
    const float* logv    = (const float*)d_in[6];
    const float* vw      = (const float*)d_in[7];
    float* out = (float*)d_out;

    k_init<<<64, 256>>>();
    k_main<<<TOTAL_BLOCKS, 256>>>(recon, gt, recon_n, gt_n, obj);
    k_epi<<<128, 256>>>(recon, gt, mean, logv, vw);
    k_final<<<1, 1>>>(out);
}

// round 4
// speedup vs baseline: 1.9649x; 1.3076x over previous
#include <cuda_runtime.h>
#include <math.h>

#define B_  32
#define NH  778
#define NO  3000
#define Z_  64
#define NPRIOR 204

#define OBJ_TILE    200
#define OBJ_TILES   4          // 800 >= 778
#define OBJ_CHUNKS  6          // 6*512 = 3072 >= 3000 (2 queries/thread)
#define OBJ_BLOCKS  (OBJ_CHUNKS * B_)            // 192
#define PRIOR_PAD   208

#define HAND_QCH    2          // 2*512 = 1024 >= 778 (2 queries/thread)
#define HAND_TSEG   3
#define HAND_SEGLEN 1000
#define HAND_TILE   200
#define HAND_BLOCKS (HAND_QCH * HAND_TSEG * B_)  // 192
#define TOTAL_BLOCKS (OBJ_BLOCKS + HAND_BLOCKS)  // 384

#define EPI_BLOCKS  96

// Per-block partials (plain stores each replay -> no init kernel needed)
__device__ float g_part[OBJ_BLOCKS][5];          // penetr, n_pts, contact, consist, loss_o
__device__ float g_mr[HAND_TSEG][B_ * NH];       // per-segment hand->obj min m (recon)
__device__ float g_mg[HAND_TSEG][B_ * NH];       // per-segment hand->obj min m (gt)
__device__ float g_epart[EPI_BLOCKS][3];         // loss_h, mse, kld

__constant__ int c_prior[NPRIOR] = {
  697,698,699,700,712,713,714,715,737,738,739,740,741,743,744,745,
  746,748,749,750,753,754,755,756,757,758,759,760,761,762,763,764,
  765,766,767,768,
  46,47,48,49,164,165,166,167,194,195,223,237,238,280,281,298,
  301,317,320,323,324,325,326,327,328,329,330,331,332,333,340,341,
  342,343,344,345,346,347,348,349,350,351,352,353,354,355,
  356,357,358,359,375,376,386,387,396,397,402,403,413,429,433,434,
  435,436,437,438,439,440,441,442,443,444,452,453,454,455,456,459,
  460,461,462,463,464,465,466,467,
  468,469,470,471,484,485,486,496,497,506,507,513,514,524,545,546,
  547,548,549,550,551,552,553,555,563,564,565,566,567,570,572,573,
  574,575,576,577,578,
  580,581,582,583,600,601,602,614,615,624,625,630,631,641,663,664,
  665,666,667,668,670,672,680,681,682,683,684,686,687,688,689,690,
  691,692,693,694,695,
  73,96,98,99,772,774,775,777
};

typedef unsigned long long u64;

__device__ __forceinline__ u64 fma2(u64 a, u64 b, u64 c) {
    u64 d;
    asm("fma.rn.f32x2 %0, %1, %2, %3;" : "=l"(d) : "l"(a), "l"(b), "l"(c));
    return d;
}
__device__ __forceinline__ u64 add2(u64 a, u64 b) {
    u64 d;
    asm("add.rn.f32x2 %0, %1, %2;" : "=l"(d) : "l"(a), "l"(b));
    return d;
}
__device__ __forceinline__ u64 pack2(float lo, float hi) {
    u64 d;
    asm("mov.b64 %0, {%1, %2};" : "=l"(d) : "r"(__float_as_uint(lo)), "r"(__float_as_uint(hi)));
    return d;
}
__device__ __forceinline__ void unpack2u(u64 v, unsigned& lo, unsigned& hi) {
    asm("mov.b64 {%0, %1}, %2;" : "=r"(lo), "=r"(hi) : "l"(v));
}

__device__ __forceinline__ float warp_sum(float v) {
#pragma unroll
    for (int o = 16; o > 0; o >>= 1) v += __shfl_down_sync(0xffffffffu, v, o);
    return v;
}
__device__ __forceinline__ float sgnf(float x) {
    return (x > 0.f) ? 1.f : ((x < 0.f) ? -1.f : 0.f);
}

struct ObjSmem {
    u64 rg[OBJ_TILE][4];    // lanes (recon, gt): {rx,gx},{ry,gy},{rz,gz},{rw,gw}
    u64 pr[PRIOR_PAD][4];   // duplicated prior pts: {x,x},{y,y},{z,z},{w,w}
};
struct HandSmem {
    u64 oo[HAND_TILE][4];   // duplicated obj pts
};
union SmemU { ObjSmem o; HandSmem h; };

__global__ void __launch_bounds__(256, 3) k_main(
    const float* __restrict__ recon, const float* __restrict__ gt,
    const float* __restrict__ recon_n, const float* __restrict__ gt_n,
    const float* __restrict__ obj)
{
    __shared__ __align__(16) SmemU S;
    __shared__ float red[8][5];
    const int tid = threadIdx.x;
    const int lane = tid & 31, warp = tid >> 5;
    const float FINF = __int_as_float(0x7F800000);

    if (blockIdx.x < OBJ_BLOCKS) {
        // =================== OBJ path ===================
        const int b     = blockIdx.x / OBJ_CHUNKS;
        const int chunk = blockIdx.x % OBJ_CHUNKS;
        const int j0 = chunk * 512 + tid;
        const int j1 = j0 + 256;
        const bool a0 = (j0 < NO), a1 = (j1 < NO);
        const int jj0 = a0 ? j0 : (NO - 1);
        const int jj1 = a1 ? j1 : (NO - 1);

        const float* ob = obj + (size_t)b * NO * 3;
        const float ox0 = ob[3*jj0], oy0 = ob[3*jj0+1], oz0 = ob[3*jj0+2];
        const float ox1 = ob[3*jj1], oy1 = ob[3*jj1+1], oz1 = ob[3*jj1+2];
        const float bq0 = 0.5f*(ox0*ox0 + oy0*oy0 + oz0*oz0);
        const float bq1 = 0.5f*(ox1*ox1 + oy1*oy1 + oz1*oz1);

        // duplicate-packed per query (lanes recon/gt share the query)
        const u64 BQ0 = pack2(bq0, bq0), NX0 = pack2(-ox0, -ox0),
                  NY0 = pack2(-oy0, -oy0), NZ0 = pack2(-oz0, -oz0);
        const u64 BQ1 = pack2(bq1, bq1), NX1 = pack2(-ox1, -ox1),
                  NY1 = pack2(-oy1, -oy1), NZ1 = pack2(-oz1, -oz1);
        // cross-query packed for prior scan (lanes q0/q1)
        const u64 BQP = pack2(bq0, bq1), NXP = pack2(-ox0, -ox1),
                  NYP = pack2(-oy0, -oy1), NZP = pack2(-oz0, -oz1);

        const float* rb = recon + (size_t)b * NH * 3;
        const float* gb = gt    + (size_t)b * NH * 3;

        // gather prior points (duplicated lanes) once
        if (tid < PRIOR_PAD) {
            float x = 0.f, y = 0.f, z = 0.f, w = FINF;
            if (tid < NPRIOR) {
                const int p = c_prior[tid];
                x = rb[3*p]; y = rb[3*p+1]; z = rb[3*p+2];
                w = 0.5f*(x*x + y*y + z*z);
            }
            float2* pp = (float2*)S.o.pr[tid];
            pp[0] = make_float2(x, x); pp[1] = make_float2(y, y);
            pp[2] = make_float2(z, z); pp[3] = make_float2(w, w);
        }

        unsigned br0 = 0xFFFFFFFFu, bg0 = 0xFFFFFFFFu;
        unsigned br1 = 0xFFFFFFFFu, bg1 = 0xFFFFFFFFu;

        for (int t = 0; t < OBJ_TILES; t++) {
            const int t0 = t * OBJ_TILE;
            __syncthreads();
            if (tid < OBJ_TILE) {
                const int tg = t0 + tid;
                float rx=0.f, ry=0.f, rz=0.f, rw=FINF, gx=0.f, gy=0.f, gz=0.f, gw=FINF;
                if (tg < NH) {
                    rx = rb[3*tg]; ry = rb[3*tg+1]; rz = rb[3*tg+2];
                    rw = 0.5f*(rx*rx + ry*ry + rz*rz);
                    gx = gb[3*tg]; gy = gb[3*tg+1]; gz = gb[3*tg+2];
                    gw = 0.5f*(gx*gx + gy*gy + gz*gz);
                }
                float2* pp = (float2*)S.o.rg[tid];
                pp[0] = make_float2(rx, gx); pp[1] = make_float2(ry, gy);
                pp[2] = make_float2(rz, gz); pp[3] = make_float2(rw, gw);
            }
            __syncthreads();
#pragma unroll 4
            for (int k = 0; k < OBJ_TILE; k++) {
                const ulonglong2 A  = *(const ulonglong2*)&S.o.rg[k][0]; // X2, Y2
                const ulonglong2 Bv = *(const ulonglong2*)&S.o.rg[k][2]; // Z2, W2
                const unsigned kb = (unsigned)(t0 + k);
                u64 M = add2(BQ0, Bv.y);
                M = fma2(NX0, A.x, M); M = fma2(NY0, A.y, M); M = fma2(NZ0, Bv.x, M);
                unsigned mr, mg; unpack2u(M, mr, mg);
                br0 = min(br0, (mr & 0xFFFFFC00u) | kb);
                bg0 = min(bg0, (mg & 0xFFFFFC00u) | kb);
                M = add2(BQ1, Bv.y);
                M = fma2(NX1, A.x, M); M = fma2(NY1, A.y, M); M = fma2(NZ1, Bv.x, M);
                unpack2u(M, mr, mg);
                br1 = min(br1, (mr & 0xFFFFFC00u) | kb);
                bg1 = min(bg1, (mg & 0xFFFFFC00u) | kb);
            }
        }

        // prior scan (packed lanes = the two queries)
        float mp0 = FINF, mp1 = FINF;
        __syncthreads();
#pragma unroll 4
        for (int k = 0; k < PRIOR_PAD; k++) {
            const ulonglong2 A  = *(const ulonglong2*)&S.o.pr[k][0];
            const ulonglong2 Bv = *(const ulonglong2*)&S.o.pr[k][2];
            u64 M = add2(BQP, Bv.y);
            M = fma2(NXP, A.x, M); M = fma2(NYP, A.y, M); M = fma2(NZP, Bv.x, M);
            unsigned u0, u1; unpack2u(M, u0, u1);
            mp0 = fminf(mp0, __uint_as_float(u0));
            mp1 = fminf(mp1, __uint_as_float(u1));
        }

        float vals[5] = {0.f, 0.f, 0.f, 0.f, 0.f};
        const float* rnb = recon_n + (size_t)b * NH * 3;
        const float* gnb = gt_n    + (size_t)b * NH * 3;
#pragma unroll
        for (int q = 0; q < 2; q++) {
            const bool act = q ? a1 : a0;
            if (!act) continue;
            const float ox = q ? ox1 : ox0, oy = q ? oy1 : oy0, oz = q ? oz1 : oz0;
            const int ir = (int)((q ? br1 : br0) & 1023u);
            const int ig = (int)((q ? bg1 : bg0) & 1023u);
            const float mp = q ? mp1 : mp0;

            float dxr = ox - rb[3*ir], dyr = oy - rb[3*ir+1], dzr = oz - rb[3*ir+2];
            float d2r = dxr*dxr + dyr*dyr + dzr*dzr;
            float dotr = rnb[3*ir]*dxr + rnb[3*ir+1]*dyr + rnb[3*ir+2]*dzr;
            float o2h = sqrtf(d2r) * sgnf(dotr);
            bool interior = (-dotr) > 0.f;

            float dxg = ox - gb[3*ig], dyg = oy - gb[3*ig+1], dzg = oz - gb[3*ig+2];
            float d2g = dxg*dxg + dyg*dyg + dzg*dzg;
            float dotg = gnb[3*ig]*dxg + gnb[3*ig+1]*dyg + gnb[3*ig+2]*dzg;
            float o2h_gt = sqrtf(d2g) * sgnf(dotg);

            float d2p = fmaxf(2.f * mp, 0.f);
            bool cmap  = sqrtf(d2g) < 0.005f;
            bool rcmap = sqrtf(d2r) < 0.005f;

            vals[0] += interior ? d2r : 0.f;
            vals[1] += cmap ? 1.f : 0.f;
            vals[2] += cmap ? d2p : 0.f;
            vals[3] += (cmap && rcmap) ? 1.f : 0.f;
            bool w_dist = (o2h_gt < 0.01f) && (o2h_gt > -0.005f);
            float w = (o2h < 0.f) ? 1.5f : (w_dist ? 1.0f : 0.1f);
            vals[4] += fabsf(o2h - o2h_gt) * w;
        }

#pragma unroll
        for (int q = 0; q < 5; q++) {
            float v = warp_sum(vals[q]);
            if (lane == 0) red[warp][q] = v;
        }
        __syncthreads();
        if (tid < 5) {
            float s = 0.f;
#pragma unroll
            for (int wi = 0; wi < 8; wi++) s += red[wi][tid];
            g_part[blockIdx.x][tid] = s;
        }
    } else {
        // =================== HAND path ===================
        const int hb  = blockIdx.x - OBJ_BLOCKS;
        const int b   = hb / (HAND_QCH * HAND_TSEG);
        const int r_  = hb % (HAND_QCH * HAND_TSEG);
        const int qc  = r_ / HAND_TSEG;
        const int ts  = r_ % HAND_TSEG;
        const int i0 = qc * 512 + tid;
        const int i1 = i0 + 256;
        const bool a0 = (i0 < NH), a1 = (i1 < NH);
        const int ii0 = a0 ? i0 : (NH - 1);
        const int ii1 = a1 ? i1 : (NH - 1);

        const float* rb = recon + (size_t)b * NH * 3;
        const float* gb = gt    + (size_t)b * NH * 3;
        const float rx0 = rb[3*ii0], ry0 = rb[3*ii0+1], rz0 = rb[3*ii0+2];
        const float gx0 = gb[3*ii0], gy0 = gb[3*ii0+1], gz0 = gb[3*ii0+2];
        const float rx1 = rb[3*ii1], ry1 = rb[3*ii1+1], rz1 = rb[3*ii1+2];
        const float gx1 = gb[3*ii1], gy1 = gb[3*ii1+1], gz1 = gb[3*ii1+2];

        // lanes = (recon-query, gt-query) for each hand index
        const u64 BQ0 = pack2(0.5f*(rx0*rx0+ry0*ry0+rz0*rz0), 0.5f*(gx0*gx0+gy0*gy0+gz0*gz0));
        const u64 NX0 = pack2(-rx0, -gx0), NY0 = pack2(-ry0, -gy0), NZ0 = pack2(-rz0, -gz0);
        const u64 BQ1 = pack2(0.5f*(rx1*rx1+ry1*ry1+rz1*rz1), 0.5f*(gx1*gx1+gy1*gy1+gz1*gz1));
        const u64 NX1 = pack2(-rx1, -gx1), NY1 = pack2(-ry1, -gy1), NZ1 = pack2(-rz1, -gz1);

        float mr0 = __int_as_float(0x7F800000), mg0 = mr0, mr1 = mr0, mg1 = mr0;
        const float* obp = obj + (size_t)b * NO * 3 + (size_t)ts * HAND_SEGLEN * 3;

        for (int t = 0; t < HAND_SEGLEN; t += HAND_TILE) {
            __syncthreads();
            if (tid < HAND_TILE) {
                const int tg = t + tid;
                float x = obp[3*tg], y = obp[3*tg+1], z = obp[3*tg+2];
                float w = 0.5f*(x*x + y*y + z*z);
                float2* pp = (float2*)S.h.oo[tid];
                pp[0] = make_float2(x, x); pp[1] = make_float2(y, y);
                pp[2] = make_float2(z, z); pp[3] = make_float2(w, w);
            }
            __syncthreads();
#pragma unroll 4
            for (int k = 0; k < HAND_TILE; k++) {
                const ulonglong2 A  = *(const ulonglong2*)&S.h.oo[k][0];
                const ulonglong2 Bv = *(const ulonglong2*)&S.h.oo[k][2];
                u64 M = add2(BQ0, Bv.y);
                M = fma2(NX0, A.x, M); M = fma2(NY0, A.y, M); M = fma2(NZ0, Bv.x, M);
                unsigned u0, u1; unpack2u(M, u0, u1);
                mr0 = fminf(mr0, __uint_as_float(u0));
                mg0 = fminf(mg0, __uint_as_float(u1));
                M = add2(BQ1, Bv.y);
                M = fma2(NX1, A.x, M); M = fma2(NY1, A.y, M); M = fma2(NZ1, Bv.x, M);
                unpack2u(M, u0, u1);
                mr1 = fminf(mr1, __uint_as_float(u0));
                mg1 = fminf(mg1, __uint_as_float(u1));
            }
        }

        if (a0) {
            g_mr[ts][b * NH + i0] = mr0;
            g_mg[ts][b * NH + i0] = mg0;
        }
        if (a1) {
            g_mr[ts][b * NH + i1] = mr1;
            g_mg[ts][b * NH + i1] = mg1;
        }
    }
}

__global__ void __launch_bounds__(256) k_epi(
    const float* __restrict__ recon, const float* __restrict__ gt,
    const float* __restrict__ mean, const float* __restrict__ logv,
    const float* __restrict__ vw)
{
    const int gid = blockIdx.x * blockDim.x + threadIdx.x;
    const int stride = gridDim.x * blockDim.x;

    float s_h = 0.f, s_rec = 0.f, s_kld = 0.f;
    for (int j = gid; j < B_ * NH; j += stride) {
        const int i = j % NH;
        float mr = fminf(fminf(g_mr[0][j], g_mr[1][j]), g_mr[2][j]);
        float mg = fminf(fminf(g_mg[0][j], g_mg[1][j]), g_mg[2][j]);
        float dr = sqrtf(fmaxf(2.f * mr, 0.f));
        float dg = sqrtf(fmaxf(2.f * mg, 0.f));
        s_h += fabsf(dr - dg) * powf(vw[i], 0.4f);
    }
    for (int i = gid; i < B_ * NH * 3; i += stride) {
        float d = recon[i] - gt[i];
        s_rec += d * d;
    }
    for (int i = gid; i < B_ * Z_; i += stride) {
        float m = mean[i], lv = logv[i];
        s_kld += 1.f + lv - m * m - expf(lv);
    }

    __shared__ float red[8][3];
    const int lane = threadIdx.x & 31, warp = threadIdx.x >> 5;
    float v0 = warp_sum(s_h), v1 = warp_sum(s_rec), v2 = warp_sum(s_kld);
    if (lane == 0) { red[warp][0] = v0; red[warp][1] = v1; red[warp][2] = v2; }
    __syncthreads();
    if (threadIdx.x < 3) {
        float s = 0.f;
#pragma unroll
        for (int wi = 0; wi < 8; wi++) s += red[wi][threadIdx.x];
        g_epart[blockIdx.x][threadIdx.x] = s;
    }
}

__global__ void k_final(float* out) {
    __shared__ float red[8][8];
    const int tid = threadIdx.x;
    const int lane = tid & 31, warp = tid >> 5;

    float a[8] = {0.f, 0.f, 0.f, 0.f, 0.f, 0.f, 0.f, 0.f};
    for (int i = tid; i < OBJ_BLOCKS; i += 256) {
#pragma unroll
        for (int q = 0; q < 5; q++) a[2 + q] += g_part[i][q];
    }
    for (int i = tid; i < EPI_BLOCKS; i += 256) {
        a[7] += g_epart[i][0];
        a[0] += g_epart[i][1];
        a[1] += g_epart[i][2];
    }
#pragma unroll
    for (int q = 0; q < 8; q++) {
        float v = warp_sum(a[q]);
        if (lane == 0) red[warp][q] = v;
    }
    __syncthreads();
    if (tid == 0) {
        double acc[8];
#pragma unroll
        for (int q = 0; q < 8; q++) {
            float s = 0.f;
            for (int wi = 0; wi < 8; wi++) s += red[wi][q];
            acc[q] = (double)s;
        }
        const double KLC = 0.005;
        double recon_loss = acc[0] / B_;
        double kld        = -0.5 * acc[1] / B_ * 10.0;
        double penetr     = 100.0 * acc[2] / B_;
        double npts       = acc[3];
        double contact    = 3000.0 * ((npts > 0.0) ? (acc[4] / (B_ * npts)) : 0.0);
        double consist    = -5.0 * acc[5] / (npts + 0.0001);
        double loss_o     = 30.0 * (1.0 - KLC) * acc[6] / ((double)B_ * NO);
        double loss_h     = 35.0 * (1.0 - KLC) * acc[7] / ((double)B_ * NH);
        double total = recon_loss + 0.1 * kld + 1000.0 * penetr
                     + 10.0 * contact + 10.0 * consist + (loss_h + loss_o);
        out[0] = (float)total;
    }
}

extern "C" void kernel_launch(void* const* d_in, const int* in_sizes, int n_in,
                              void* d_out, int out_size) {
    const float* recon   = (const float*)d_in[0];
    const float* gt      = (const float*)d_in[1];
    const float* recon_n = (const float*)d_in[2];
    const float* gt_n    = (const float*)d_in[3];
    const float* obj     = (const float*)d_in[4];
    const float* mean    = (const float*)d_in[5];
    const float* logv    = (const float*)d_in[6];
    const float* vw      = (const float*)d_in[7];
    float* out = (float*)d_out;

    k_main<<<TOTAL_BLOCKS, 256>>>(recon, gt, recon_n, gt_n, obj);
    k_epi<<<EPI_BLOCKS, 256>>>(recon, gt, mean, logv, vw);
    k_final<<<1, 256>>>(out);
}

// round 5
// speedup vs baseline: 2.0562x; 1.0465x over previous
#include <cuda_runtime.h>
#include <math.h>

#define B_  32
#define NH  778
#define NO  3000
#define Z_  64
#define NPRIOR 204

#define OBJ_TILE    200
#define OBJ_CHUNKS  6           // 6*512 = 3072 >= 3000 (2 queries/thread)
#define OBJ_SEGS    2           // seg0: targets [0,400), seg1: [400,778) + prior
#define OBJ_BLOCKS  (OBJ_CHUNKS * B_ * OBJ_SEGS)     // 384
#define PRIOR_PAD   208

#define HAND_QCH    2           // 2*512 = 1024 >= 778 (2 queries/thread)
#define HAND_TSEG   6
#define HAND_SEGLEN 500
#define HAND_TILE   250
#define HAND_BLOCKS (HAND_QCH * HAND_TSEG * B_)      // 384
#define TOTAL_BLOCKS (OBJ_BLOCKS + HAND_BLOCKS)      // 768

#define EPI_BLOCKS  192

// Per-segment results (plain stores each replay; merged in k_epi)
__device__ unsigned g_okr[OBJ_SEGS][B_ * NO];   // obj->recon argmin keys
__device__ unsigned g_okg[OBJ_SEGS][B_ * NO];   // obj->gt argmin keys
__device__ float    g_mp[B_ * NO];              // obj->prior min m (seg1 writes)
__device__ float    g_mr[HAND_TSEG][B_ * NH];   // hand(recon)->obj min m
__device__ float    g_mg[HAND_TSEG][B_ * NH];   // hand(gt)->obj min m
__device__ float    g_epart[EPI_BLOCKS][8];
__device__ unsigned g_ctr;                      // self-resetting election counter

__constant__ int c_prior[NPRIOR] = {
  697,698,699,700,712,713,714,715,737,738,739,740,741,743,744,745,
  746,748,749,750,753,754,755,756,757,758,759,760,761,762,763,764,
  765,766,767,768,
  46,47,48,49,164,165,166,167,194,195,223,237,238,280,281,298,
  301,317,320,323,324,325,326,327,328,329,330,331,332,333,340,341,
  342,343,344,345,346,347,348,349,350,351,352,353,354,355,
  356,357,358,359,375,376,386,387,396,397,402,403,413,429,433,434,
  435,436,437,438,439,440,441,442,443,444,452,453,454,455,456,459,
  460,461,462,463,464,465,466,467,
  468,469,470,471,484,485,486,496,497,506,507,513,514,524,545,546,
  547,548,549,550,551,552,553,555,563,564,565,566,567,570,572,573,
  574,575,576,577,578,
  580,581,582,583,600,601,602,614,615,624,625,630,631,641,663,664,
  665,666,667,668,670,672,680,681,682,683,684,686,687,688,689,690,
  691,692,693,694,695,
  73,96,98,99,772,774,775,777
};

typedef unsigned long long u64;

__device__ __forceinline__ u64 fma2(u64 a, u64 b, u64 c) {
    u64 d;
    asm("fma.rn.f32x2 %0, %1, %2, %3;" : "=l"(d) : "l"(a), "l"(b), "l"(c));
    return d;
}
__device__ __forceinline__ u64 add2(u64 a, u64 b) {
    u64 d;
    asm("add.rn.f32x2 %0, %1, %2;" : "=l"(d) : "l"(a), "l"(b));
    return d;
}
__device__ __forceinline__ u64 pack2(float lo, float hi) {
    u64 d;
    asm("mov.b64 %0, {%1, %2};" : "=l"(d) : "r"(__float_as_uint(lo)), "r"(__float_as_uint(hi)));
    return d;
}
__device__ __forceinline__ void unpack2u(u64 v, unsigned& lo, unsigned& hi) {
    asm("mov.b64 {%0, %1}, %2;" : "=r"(lo), "=r"(hi) : "l"(v));
}
__device__ __forceinline__ float warp_sum(float v) {
#pragma unroll
    for (int o = 16; o > 0; o >>= 1) v += __shfl_down_sync(0xffffffffu, v, o);
    return v;
}
__device__ __forceinline__ float sgnf(float x) {
    return (x > 0.f) ? 1.f : ((x < 0.f) ? -1.f : 0.f);
}

struct ObjSmem {
    u64 rg[OBJ_TILE][4];    // lanes (recon, gt)
    u64 pr[PRIOR_PAD][4];   // duplicated prior points
};
struct HandSmem {
    u64 oo[HAND_TILE][4];   // duplicated obj points
};
union SmemU { ObjSmem o; HandSmem h; };

__global__ void __launch_bounds__(256, 4) k_main(
    const float* __restrict__ recon, const float* __restrict__ gt,
    const float* __restrict__ obj)
{
    __shared__ __align__(16) SmemU S;
    const int tid = threadIdx.x;
    const float FINF = __int_as_float(0x7F800000);

    if (blockIdx.x < OBJ_BLOCKS) {
        // =================== OBJ path: one target segment ===================
        const int seg   = blockIdx.x & 1;
        const int rest  = blockIdx.x >> 1;
        const int chunk = rest % OBJ_CHUNKS;
        const int b     = rest / OBJ_CHUNKS;
        const int j0 = chunk * 512 + tid;
        const int j1 = j0 + 256;
        const bool a0 = (j0 < NO), a1 = (j1 < NO);
        const int jj0 = a0 ? j0 : (NO - 1);
        const int jj1 = a1 ? j1 : (NO - 1);

        const float* ob = obj + (size_t)b * NO * 3;
        const float ox0 = ob[3*jj0], oy0 = ob[3*jj0+1], oz0 = ob[3*jj0+2];
        const float ox1 = ob[3*jj1], oy1 = ob[3*jj1+1], oz1 = ob[3*jj1+2];
        const float bq0 = 0.5f*(ox0*ox0 + oy0*oy0 + oz0*oz0);
        const float bq1 = 0.5f*(ox1*ox1 + oy1*oy1 + oz1*oz1);

        const u64 BQ0 = pack2(bq0, bq0), NX0 = pack2(-ox0, -ox0),
                  NY0 = pack2(-oy0, -oy0), NZ0 = pack2(-oz0, -oz0);
        const u64 BQ1 = pack2(bq1, bq1), NX1 = pack2(-ox1, -ox1),
                  NY1 = pack2(-oy1, -oy1), NZ1 = pack2(-oz1, -oz1);

        const float* rb = recon + (size_t)b * NH * 3;
        const float* gb = gt    + (size_t)b * NH * 3;

        if (seg == 1 && tid < PRIOR_PAD) {
            float x = 0.f, y = 0.f, z = 0.f, w = FINF;
            if (tid < NPRIOR) {
                const int p = c_prior[tid];
                x = rb[3*p]; y = rb[3*p+1]; z = rb[3*p+2];
                w = 0.5f*(x*x + y*y + z*z);
            }
            float2* pp = (float2*)S.o.pr[tid];
            pp[0] = make_float2(x, x); pp[1] = make_float2(y, y);
            pp[2] = make_float2(z, z); pp[3] = make_float2(w, w);
        }

        unsigned br0 = 0xFFFFFFFFu, bg0 = 0xFFFFFFFFu;
        unsigned br1 = 0xFFFFFFFFu, bg1 = 0xFFFFFFFFu;
        const int tbase = seg * 400;

        for (int t = 0; t < 2; t++) {
            const int t0 = tbase + t * OBJ_TILE;
            __syncthreads();
            if (tid < OBJ_TILE) {
                const int tg = t0 + tid;
                float rx=0.f, ry=0.f, rz=0.f, rw=FINF, gx=0.f, gy=0.f, gz=0.f, gw=FINF;
                if (tg < NH) {
                    rx = rb[3*tg]; ry = rb[3*tg+1]; rz = rb[3*tg+2];
                    rw = 0.5f*(rx*rx + ry*ry + rz*rz);
                    gx = gb[3*tg]; gy = gb[3*tg+1]; gz = gb[3*tg+2];
                    gw = 0.5f*(gx*gx + gy*gy + gz*gz);
                }
                float2* pp = (float2*)S.o.rg[tid];
                pp[0] = make_float2(rx, gx); pp[1] = make_float2(ry, gy);
                pp[2] = make_float2(rz, gz); pp[3] = make_float2(rw, gw);
            }
            __syncthreads();
#pragma unroll 4
            for (int k = 0; k < OBJ_TILE; k++) {
                const ulonglong2 A  = *(const ulonglong2*)&S.o.rg[k][0];
                const ulonglong2 Bv = *(const ulonglong2*)&S.o.rg[k][2];
                const unsigned kb = (unsigned)(t0 + k);
                u64 M = add2(BQ0, Bv.y);
                M = fma2(NX0, A.x, M); M = fma2(NY0, A.y, M); M = fma2(NZ0, Bv.x, M);
                unsigned mr, mg; unpack2u(M, mr, mg);
                br0 = min(br0, (mr & 0xFFFFFC00u) | kb);
                bg0 = min(bg0, (mg & 0xFFFFFC00u) | kb);
                M = add2(BQ1, Bv.y);
                M = fma2(NX1, A.x, M); M = fma2(NY1, A.y, M); M = fma2(NZ1, Bv.x, M);
                unpack2u(M, mr, mg);
                br1 = min(br1, (mr & 0xFFFFFC00u) | kb);
                bg1 = min(bg1, (mg & 0xFFFFFC00u) | kb);
            }
        }

        if (a0) { g_okr[seg][b * NO + j0] = br0; g_okg[seg][b * NO + j0] = bg0; }
        if (a1) { g_okr[seg][b * NO + j1] = br1; g_okg[seg][b * NO + j1] = bg1; }

        if (seg == 1) {
            // prior scan (packed lanes = the two queries)
            const u64 BQP = pack2(bq0, bq1), NXP = pack2(-ox0, -ox1),
                      NYP = pack2(-oy0, -oy1), NZP = pack2(-oz0, -oz1);
            float mp0 = FINF, mp1 = FINF;
            __syncthreads();
#pragma unroll 4
            for (int k = 0; k < PRIOR_PAD; k++) {
                const ulonglong2 A  = *(const ulonglong2*)&S.o.pr[k][0];
                const ulonglong2 Bv = *(const ulonglong2*)&S.o.pr[k][2];
                u64 M = add2(BQP, Bv.y);
                M = fma2(NXP, A.x, M); M = fma2(NYP, A.y, M); M = fma2(NZP, Bv.x, M);
                unsigned u0, u1; unpack2u(M, u0, u1);
                mp0 = fminf(mp0, __uint_as_float(u0));
                mp1 = fminf(mp1, __uint_as_float(u1));
            }
            if (a0) g_mp[b * NO + j0] = mp0;
            if (a1) g_mp[b * NO + j1] = mp1;
        }
    } else {
        // =================== HAND path: one target segment ===================
        const int hb  = blockIdx.x - OBJ_BLOCKS;
        const int ts  = hb % HAND_TSEG;
        const int rest = hb / HAND_TSEG;
        const int qc  = rest % HAND_QCH;
        const int b   = rest / HAND_QCH;
        const int i0 = qc * 512 + tid;
        const int i1 = i0 + 256;
        const bool a0 = (i0 < NH), a1 = (i1 < NH);
        const int ii0 = a0 ? i0 : (NH - 1);
        const int ii1 = a1 ? i1 : (NH - 1);

        const float* rb = recon + (size_t)b * NH * 3;
        const float* gb = gt    + (size_t)b * NH * 3;
        const float rx0 = rb[3*ii0], ry0 = rb[3*ii0+1], rz0 = rb[3*ii0+2];
        const float gx0 = gb[3*ii0], gy0 = gb[3*ii0+1], gz0 = gb[3*ii0+2];
        const float rx1 = rb[3*ii1], ry1 = rb[3*ii1+1], rz1 = rb[3*ii1+2];
        const float gx1 = gb[3*ii1], gy1 = gb[3*ii1+1], gz1 = gb[3*ii1+2];

        const u64 BQ0 = pack2(0.5f*(rx0*rx0+ry0*ry0+rz0*rz0), 0.5f*(gx0*gx0+gy0*gy0+gz0*gz0));
        const u64 NX0 = pack2(-rx0, -gx0), NY0 = pack2(-ry0, -gy0), NZ0 = pack2(-rz0, -gz0);
        const u64 BQ1 = pack2(0.5f*(rx1*rx1+ry1*ry1+rz1*rz1), 0.5f*(gx1*gx1+gy1*gy1+gz1*gz1));
        const u64 NX1 = pack2(-rx1, -gx1), NY1 = pack2(-ry1, -gy1), NZ1 = pack2(-rz1, -gz1);

        float mr0 = FINF, mg0 = FINF, mr1 = FINF, mg1 = FINF;
        const float* obp = obj + (size_t)b * NO * 3 + (size_t)ts * HAND_SEGLEN * 3;

        for (int t = 0; t < HAND_SEGLEN; t += HAND_TILE) {
            __syncthreads();
            if (tid < HAND_TILE) {
                const int tg = t + tid;
                float x = obp[3*tg], y = obp[3*tg+1], z = obp[3*tg+2];
                float w = 0.5f*(x*x + y*y + z*z);
                float2* pp = (float2*)S.h.oo[tid];
                pp[0] = make_float2(x, x); pp[1] = make_float2(y, y);
                pp[2] = make_float2(z, z); pp[3] = make_float2(w, w);
            }
            __syncthreads();
#pragma unroll 4
            for (int k = 0; k < HAND_TILE; k++) {
                const ulonglong2 A  = *(const ulonglong2*)&S.h.oo[k][0];
                const ulonglong2 Bv = *(const ulonglong2*)&S.h.oo[k][2];
                u64 M = add2(BQ0, Bv.y);
                M = fma2(NX0, A.x, M); M = fma2(NY0, A.y, M); M = fma2(NZ0, Bv.x, M);
                unsigned u0, u1; unpack2u(M, u0, u1);
                mr0 = fminf(mr0, __uint_as_float(u0));
                mg0 = fminf(mg0, __uint_as_float(u1));
                M = add2(BQ1, Bv.y);
                M = fma2(NX1, A.x, M); M = fma2(NY1, A.y, M); M = fma2(NZ1, Bv.x, M);
                unpack2u(M, u0, u1);
                mr1 = fminf(mr1, __uint_as_float(u0));
                mg1 = fminf(mg1, __uint_as_float(u1));
            }
        }

        if (a0) { g_mr[ts][b * NH + i0] = mr0; g_mg[ts][b * NH + i0] = mg0; }
        if (a1) { g_mr[ts][b * NH + i1] = mr1; g_mg[ts][b * NH + i1] = mg1; }
    }
}

// Epilogue + final combine (last-block election)
__global__ void __launch_bounds__(256) k_epi(
    const float* __restrict__ recon, const float* __restrict__ gt,
    const float* __restrict__ recon_n, const float* __restrict__ gt_n,
    const float* __restrict__ obj,
    const float* __restrict__ mean, const float* __restrict__ logv,
    const float* __restrict__ vw, float* __restrict__ out)
{
    const int gid = blockIdx.x * blockDim.x + threadIdx.x;
    const int stride = gridDim.x * blockDim.x;
    const int tid = threadIdx.x;

    // a: penetr, n_pts, contact, consist, loss_o, loss_h, mse, kld
    float a[8] = {0.f,0.f,0.f,0.f,0.f,0.f,0.f,0.f};

    // ---- obj-side terms ----
    for (int idx = gid; idx < B_ * NO; idx += stride) {
        const int b = idx / NO;
        const int j = idx - b * NO;
        const float* ob = obj + (size_t)b * NO * 3;
        const float ox = ob[3*j], oy = ob[3*j+1], oz = ob[3*j+2];
        const unsigned br = min(g_okr[0][idx], g_okr[1][idx]);
        const unsigned bg = min(g_okg[0][idx], g_okg[1][idx]);
        const int ir = (int)(br & 1023u);
        const int ig = (int)(bg & 1023u);
        const float mp = g_mp[idx];

        const float* rb  = recon   + (size_t)b * NH * 3;
        const float* gb  = gt      + (size_t)b * NH * 3;
        const float* rnb = recon_n + (size_t)b * NH * 3;
        const float* gnb = gt_n    + (size_t)b * NH * 3;

        float dxr = ox - rb[3*ir], dyr = oy - rb[3*ir+1], dzr = oz - rb[3*ir+2];
        float d2r = dxr*dxr + dyr*dyr + dzr*dzr;
        float dotr = rnb[3*ir]*dxr + rnb[3*ir+1]*dyr + rnb[3*ir+2]*dzr;
        float o2h = sqrtf(d2r) * sgnf(dotr);
        bool interior = (-dotr) > 0.f;

        float dxg = ox - gb[3*ig], dyg = oy - gb[3*ig+1], dzg = oz - gb[3*ig+2];
        float d2g = dxg*dxg + dyg*dyg + dzg*dzg;
        float dotg = gnb[3*ig]*dxg + gnb[3*ig+1]*dyg + gnb[3*ig+2]*dzg;
        float o2h_gt = sqrtf(d2g) * sgnf(dotg);

        float d2p = fmaxf(2.f * mp, 0.f);
        bool cmap  = sqrtf(d2g) < 0.005f;
        bool rcmap = sqrtf(d2r) < 0.005f;

        a[0] += interior ? d2r : 0.f;
        a[1] += cmap ? 1.f : 0.f;
        a[2] += cmap ? d2p : 0.f;
        a[3] += (cmap && rcmap) ? 1.f : 0.f;
        bool w_dist = (o2h_gt < 0.01f) && (o2h_gt > -0.005f);
        float w = (o2h < 0.f) ? 1.5f : (w_dist ? 1.0f : 0.1f);
        a[4] += fabsf(o2h - o2h_gt) * w;
    }

    // ---- hand-side loss_h ----
    for (int j = gid; j < B_ * NH; j += stride) {
        const int i = j % NH;
        float mr = fminf(fminf(g_mr[0][j], g_mr[1][j]),
                   fminf(fminf(g_mr[2][j], g_mr[3][j]), fminf(g_mr[4][j], g_mr[5][j])));
        float mg = fminf(fminf(g_mg[0][j], g_mg[1][j]),
                   fminf(fminf(g_mg[2][j], g_mg[3][j]), fminf(g_mg[4][j], g_mg[5][j])));
        float dr = sqrtf(fmaxf(2.f * mr, 0.f));
        float dg = sqrtf(fmaxf(2.f * mg, 0.f));
        a[5] += fabsf(dr - dg) * powf(vw[i], 0.4f);
    }

    // ---- MSE + KLD ----
    for (int i = gid; i < B_ * NH * 3; i += stride) {
        float d = recon[i] - gt[i];
        a[6] += d * d;
    }
    for (int i = gid; i < B_ * Z_; i += stride) {
        float m = mean[i], lv = logv[i];
        a[7] += 1.f + lv - m * m - expf(lv);
    }

    __shared__ float red[8][8];
    __shared__ bool s_last;
    const int lane = tid & 31, warp = tid >> 5;
#pragma unroll
    for (int q = 0; q < 8; q++) {
        float v = warp_sum(a[q]);
        if (lane == 0) red[warp][q] = v;
    }
    __syncthreads();
    if (tid < 8) {
        float s = 0.f;
#pragma unroll
        for (int wi = 0; wi < 8; wi++) s += red[wi][tid];
        g_epart[blockIdx.x][tid] = s;
    }
    if (tid == 0) {
        __threadfence();
        unsigned t = atomicAdd(&g_ctr, 1u);
        s_last = (t == (unsigned)(gridDim.x - 1));
    }
    __syncthreads();

    if (s_last) {
        __threadfence();
        float p[8] = {0.f,0.f,0.f,0.f,0.f,0.f,0.f,0.f};
        for (int i = tid; i < EPI_BLOCKS; i += 256) {
#pragma unroll
            for (int q = 0; q < 8; q++) p[q] += g_epart[i][q];
        }
#pragma unroll
        for (int q = 0; q < 8; q++) {
            float v = warp_sum(p[q]);
            if (lane == 0) red[warp][q] = v;
        }
        __syncthreads();
        if (tid == 0) {
            double acc[8];
#pragma unroll
            for (int q = 0; q < 8; q++) {
                float s = 0.f;
                for (int wi = 0; wi < 8; wi++) s += red[wi][q];
                acc[q] = (double)s;
            }
            const double KLC = 0.005;
            double recon_loss = acc[6] / B_;
            double kld        = -0.5 * acc[7] / B_ * 10.0;
            double penetr     = 100.0 * acc[0] / B_;
            double npts       = acc[1];
            double contact    = 3000.0 * ((npts > 0.0) ? (acc[2] / (B_ * npts)) : 0.0);
            double consist    = -5.0 * acc[3] / (npts + 0.0001);
            double loss_o     = 30.0 * (1.0 - KLC) * acc[4] / ((double)B_ * NO);
            double loss_h     = 35.0 * (1.0 - KLC) * acc[5] / ((double)B_ * NH);
            double total = recon_loss + 0.1 * kld + 1000.0 * penetr
                         + 10.0 * contact + 10.0 * consist + (loss_h + loss_o);
            out[0] = (float)total;
            g_ctr = 0u;   // reset for next graph replay
        }
    }
}

extern "C" void kernel_launch(void* const* d_in, const int* in_sizes, int n_in,
                              void* d_out, int out_size) {
    const float* recon   = (const float*)d_in[0];
    const float* gt      = (const float*)d_in[1];
    const float* recon_n = (const float*)d_in[2];
    const float* gt_n    = (const float*)d_in[3];
    const float* obj     = (const float*)d_in[4];
    const float* mean    = (const float*)d_in[5];
    const float* logv    = (const float*)d_in[6];
    const float* vw      = (const float*)d_in[7];
    float* out = (float*)d_out;

    k_main<<<TOTAL_BLOCKS, 256>>>(recon, gt, obj);
    k_epi<<<EPI_BLOCKS, 256>>>(recon, gt, recon_n, gt_n, obj, mean, logv, vw, out);
}

// round 7
// speedup vs baseline: 2.1614x; 1.0512x over previous
#include <cuda_runtime.h>
#include <math.h>

#define B_  32
#define NH  778
#define NO  3000
#define Z_  64
#define NPRIOR 204

#define OBJ_SEGS    4
#define OBJ_SEGLEN  200        // seg3 covers [600,778) padded to 200
#define OBJ_CHUNKS  6          // 6*512 = 3072 >= 3000 (2 queries/thread)
#define OBJ_ITEMS   (OBJ_SEGS * OBJ_CHUNKS * B_)    // 768
#define PRIOR_PAD   208
#define PRIOR_ITEMS (OBJ_CHUNKS * B_)               // 192
#define HAND_TSEG   12
#define HAND_SEGLEN 250
#define HAND_QCH    2          // 2*512 = 1024 >= 778
#define HAND_ITEMS  (HAND_TSEG * HAND_QCH * B_)     // 768
#define TOTAL_ITEMS (OBJ_ITEMS + PRIOR_ITEMS + HAND_ITEMS)  // 1728

#define EPI_BLOCKS  592

// Per-segment results (plain stores each replay; merged in k_epi)
__device__ unsigned g_okr[OBJ_SEGS][B_ * NO];
__device__ unsigned g_okg[OBJ_SEGS][B_ * NO];
__device__ float    g_mp[B_ * NO];
__device__ float    g_mr[HAND_TSEG][B_ * NH];
__device__ float    g_mg[HAND_TSEG][B_ * NH];
__device__ float    g_epart[EPI_BLOCKS][8];
__device__ unsigned g_ctr;

__constant__ int c_prior[NPRIOR] = {
  697,698,699,700,712,713,714,715,737,738,739,740,741,743,744,745,
  746,748,749,750,753,754,755,756,757,758,759,760,761,762,763,764,
  765,766,767,768,
  46,47,48,49,164,165,166,167,194,195,223,237,238,280,281,298,
  301,317,320,323,324,325,326,327,328,329,330,331,332,333,340,341,
  342,343,344,345,346,347,348,349,350,351,352,353,354,355,
  356,357,358,359,375,376,386,387,396,397,402,403,413,429,433,434,
  435,436,437,438,439,440,441,442,443,444,452,453,454,455,456,459,
  460,461,462,463,464,465,466,467,
  468,469,470,471,484,485,486,496,497,506,507,513,514,524,545,546,
  547,548,549,550,551,552,553,555,563,564,565,566,567,570,572,573,
  574,575,576,577,578,
  580,581,582,583,600,601,602,614,615,624,625,630,631,641,663,664,
  665,666,667,668,670,672,680,681,682,683,684,686,687,688,689,690,
  691,692,693,694,695,
  73,96,98,99,772,774,775,777
};

typedef unsigned long long u64;

__device__ __forceinline__ u64 fma2(u64 a, u64 b, u64 c) {
    u64 d;
    asm("fma.rn.f32x2 %0, %1, %2, %3;" : "=l"(d) : "l"(a), "l"(b), "l"(c));
    return d;
}
__device__ __forceinline__ u64 add2(u64 a, u64 b) {
    u64 d;
    asm("add.rn.f32x2 %0, %1, %2;" : "=l"(d) : "l"(a), "l"(b));
    return d;
}
__device__ __forceinline__ u64 pack2(float lo, float hi) {
    u64 d;
    asm("mov.b64 %0, {%1, %2};" : "=l"(d) : "r"(__float_as_uint(lo)), "r"(__float_as_uint(hi)));
    return d;
}
__device__ __forceinline__ void unpack2u(u64 v, unsigned& lo, unsigned& hi) {
    asm("mov.b64 {%0, %1}, %2;" : "=r"(lo), "=r"(hi) : "l"(v));
}
__device__ __forceinline__ float warp_sum(float v) {
#pragma unroll
    for (int o = 16; o > 0; o >>= 1) v += __shfl_down_sync(0xffffffffu, v, o);
    return v;
}
__device__ __forceinline__ float sgnf(float x) {
    return (x > 0.f) ? 1.f : ((x < 0.f) ? -1.f : 0.f);
}

__global__ void __launch_bounds__(256, 4) k_main(
    const float* __restrict__ recon, const float* __restrict__ gt,
    const float* __restrict__ obj)
{
    __shared__ __align__(16) u64 T[HAND_SEGLEN][4];   // 250 rows x 32B
    const int tid = threadIdx.x;
    const float FINF = __int_as_float(0x7F800000);
    const int item = blockIdx.x;

    if (item < OBJ_ITEMS) {
        // ============ OBJ: one target segment of ~200, 512 queries ============
        const int seg   = item & 3;
        const int rest  = item >> 2;
        const int chunk = rest % OBJ_CHUNKS;
        const int b     = rest / OBJ_CHUNKS;
        const int j0 = chunk * 512 + tid;
        const int j1 = j0 + 256;
        const bool a0 = (j0 < NO), a1 = (j1 < NO);
        const int jj0 = a0 ? j0 : (NO - 1);
        const int jj1 = a1 ? j1 : (NO - 1);

        const float* ob = obj + (size_t)b * NO * 3;
        const float ox0 = ob[3*jj0], oy0 = ob[3*jj0+1], oz0 = ob[3*jj0+2];
        const float ox1 = ob[3*jj1], oy1 = ob[3*jj1+1], oz1 = ob[3*jj1+2];
        const float bq0 = 0.5f*(ox0*ox0 + oy0*oy0 + oz0*oz0);
        const float bq1 = 0.5f*(ox1*ox1 + oy1*oy1 + oz1*oz1);

        const u64 BQ0 = pack2(bq0, bq0), NX0 = pack2(-ox0, -ox0),
                  NY0 = pack2(-oy0, -oy0), NZ0 = pack2(-oz0, -oz0);
        const u64 BQ1 = pack2(bq1, bq1), NX1 = pack2(-ox1, -ox1),
                  NY1 = pack2(-oy1, -oy1), NZ1 = pack2(-oz1, -oz1);

        const float* rb = recon + (size_t)b * NH * 3;
        const float* gb = gt    + (size_t)b * NH * 3;
        const int t0 = seg * OBJ_SEGLEN;

        if (tid < OBJ_SEGLEN) {
            const int tg = t0 + tid;
            float rx=0.f, ry=0.f, rz=0.f, rw=FINF, gx=0.f, gy=0.f, gz=0.f, gw=FINF;
            if (tg < NH) {
                rx = rb[3*tg]; ry = rb[3*tg+1]; rz = rb[3*tg+2];
                rw = 0.5f*(rx*rx + ry*ry + rz*rz);
                gx = gb[3*tg]; gy = gb[3*tg+1]; gz = gb[3*tg+2];
                gw = 0.5f*(gx*gx + gy*gy + gz*gz);
            }
            float2* pp = (float2*)T[tid];
            pp[0] = make_float2(rx, gx); pp[1] = make_float2(ry, gy);
            pp[2] = make_float2(rz, gz); pp[3] = make_float2(rw, gw);
        }
        __syncthreads();

        unsigned br0 = 0xFFFFFFFFu, bg0 = 0xFFFFFFFFu;
        unsigned br1 = 0xFFFFFFFFu, bg1 = 0xFFFFFFFFu;
#pragma unroll 4
        for (int k = 0; k < OBJ_SEGLEN; k++) {
            const ulonglong2 A  = *(const ulonglong2*)&T[k][0];
            const ulonglong2 Bv = *(const ulonglong2*)&T[k][2];
            const unsigned kb = (unsigned)(t0 + k);
            u64 M = add2(BQ0, Bv.y);
            M = fma2(NX0, A.x, M); M = fma2(NY0, A.y, M); M = fma2(NZ0, Bv.x, M);
            unsigned mr, mg; unpack2u(M, mr, mg);
            br0 = min(br0, (mr & 0xFFFFFC00u) | kb);
            bg0 = min(bg0, (mg & 0xFFFFFC00u) | kb);
            M = add2(BQ1, Bv.y);
            M = fma2(NX1, A.x, M); M = fma2(NY1, A.y, M); M = fma2(NZ1, Bv.x, M);
            unpack2u(M, mr, mg);
            br1 = min(br1, (mr & 0xFFFFFC00u) | kb);
            bg1 = min(bg1, (mg & 0xFFFFFC00u) | kb);
        }
        if (a0) { g_okr[seg][b * NO + j0] = br0; g_okg[seg][b * NO + j0] = bg0; }
        if (a1) { g_okr[seg][b * NO + j1] = br1; g_okg[seg][b * NO + j1] = bg1; }
    } else if (item < OBJ_ITEMS + PRIOR_ITEMS) {
        // ============ PRIOR: 204 targets, 512 queries ============
        const int idx   = item - OBJ_ITEMS;
        const int chunk = idx % OBJ_CHUNKS;
        const int b     = idx / OBJ_CHUNKS;
        const int j0 = chunk * 512 + tid;
        const int j1 = j0 + 256;
        const bool a0 = (j0 < NO), a1 = (j1 < NO);
        const int jj0 = a0 ? j0 : (NO - 1);
        const int jj1 = a1 ? j1 : (NO - 1);

        const float* ob = obj + (size_t)b * NO * 3;
        const float ox0 = ob[3*jj0], oy0 = ob[3*jj0+1], oz0 = ob[3*jj0+2];
        const float ox1 = ob[3*jj1], oy1 = ob[3*jj1+1], oz1 = ob[3*jj1+2];
        const float bq0 = 0.5f*(ox0*ox0 + oy0*oy0 + oz0*oz0);
        const float bq1 = 0.5f*(ox1*ox1 + oy1*oy1 + oz1*oz1);
        // packed lanes = (q0, q1)
        const u64 BQP = pack2(bq0, bq1), NXP = pack2(-ox0, -ox1),
                  NYP = pack2(-oy0, -oy1), NZP = pack2(-oz0, -oz1);

        const float* rb = recon + (size_t)b * NH * 3;
        if (tid < PRIOR_PAD) {
            float x = 0.f, y = 0.f, z = 0.f, w = FINF;
            if (tid < NPRIOR) {
                const int p = c_prior[tid];
                x = rb[3*p]; y = rb[3*p+1]; z = rb[3*p+2];
                w = 0.5f*(x*x + y*y + z*z);
            }
            float2* pp = (float2*)T[tid];
            pp[0] = make_float2(x, x); pp[1] = make_float2(y, y);
            pp[2] = make_float2(z, z); pp[3] = make_float2(w, w);
        }
        __syncthreads();

        float mp0 = FINF, mp1 = FINF;
#pragma unroll 4
        for (int k = 0; k < PRIOR_PAD; k++) {
            const ulonglong2 A  = *(const ulonglong2*)&T[k][0];
            const ulonglong2 Bv = *(const ulonglong2*)&T[k][2];
            u64 M = add2(BQP, Bv.y);
            M = fma2(NXP, A.x, M); M = fma2(NYP, A.y, M); M = fma2(NZP, Bv.x, M);
            unsigned u0, u1; unpack2u(M, u0, u1);
            mp0 = fminf(mp0, __uint_as_float(u0));
            mp1 = fminf(mp1, __uint_as_float(u1));
        }
        if (a0) g_mp[b * NO + j0] = mp0;
        if (a1) g_mp[b * NO + j1] = mp1;
    } else {
        // ============ HAND: one obj segment of 250, 512 hand queries ============
        const int idx  = item - OBJ_ITEMS - PRIOR_ITEMS;
        const int ts   = idx % HAND_TSEG;
        const int rest = idx / HAND_TSEG;
        const int qc   = rest % HAND_QCH;
        const int b    = rest / HAND_QCH;
        const int i0 = qc * 512 + tid;
        const int i1 = i0 + 256;
        const bool a0 = (i0 < NH), a1 = (i1 < NH);
        const int ii0 = a0 ? i0 : (NH - 1);
        const int ii1 = a1 ? i1 : (NH - 1);

        const float* rb = recon + (size_t)b * NH * 3;
        const float* gb = gt    + (size_t)b * NH * 3;
        const float rx0 = rb[3*ii0], ry0 = rb[3*ii0+1], rz0 = rb[3*ii0+2];
        const float gx0 = gb[3*ii0], gy0 = gb[3*ii0+1], gz0 = gb[3*ii0+2];
        const float rx1 = rb[3*ii1], ry1 = rb[3*ii1+1], rz1 = rb[3*ii1+2];
        const float gx1 = gb[3*ii1], gy1 = gb[3*ii1+1], gz1 = gb[3*ii1+2];

        // packed lanes = (recon-query, gt-query)
        const u64 BQ0 = pack2(0.5f*(rx0*rx0+ry0*ry0+rz0*rz0), 0.5f*(gx0*gx0+gy0*gy0+gz0*gz0));
        const u64 NX0 = pack2(-rx0, -gx0), NY0 = pack2(-ry0, -gy0), NZ0 = pack2(-rz0, -gz0);
        const u64 BQ1 = pack2(0.5f*(rx1*rx1+ry1*ry1+rz1*rz1), 0.5f*(gx1*gx1+gy1*gy1+gz1*gz1));
        const u64 NX1 = pack2(-rx1, -gx1), NY1 = pack2(-ry1, -gy1), NZ1 = pack2(-rz1, -gz1);

        const float* obp = obj + (size_t)b * NO * 3 + (size_t)ts * HAND_SEGLEN * 3;
        if (tid < HAND_SEGLEN) {
            float x = obp[3*tid], y = obp[3*tid+1], z = obp[3*tid+2];
            float w = 0.5f*(x*x + y*y + z*z);
            float2* pp = (float2*)T[tid];
            pp[0] = make_float2(x, x); pp[1] = make_float2(y, y);
            pp[2] = make_float2(z, z); pp[3] = make_float2(w, w);
        }
        __syncthreads();

        float mr0 = FINF, mg0 = FINF, mr1 = FINF, mg1 = FINF;
#pragma unroll 5
        for (int k = 0; k < HAND_SEGLEN; k++) {
            const ulonglong2 A  = *(const ulonglong2*)&T[k][0];
            const ulonglong2 Bv = *(const ulonglong2*)&T[k][2];
            u64 M = add2(BQ0, Bv.y);
            M = fma2(NX0, A.x, M); M = fma2(NY0, A.y, M); M = fma2(NZ0, Bv.x, M);
            unsigned u0, u1; unpack2u(M, u0, u1);
            mr0 = fminf(mr0, __uint_as_float(u0));
            mg0 = fminf(mg0, __uint_as_float(u1));
            M = add2(BQ1, Bv.y);
            M = fma2(NX1, A.x, M); M = fma2(NY1, A.y, M); M = fma2(NZ1, Bv.x, M);
            unpack2u(M, u0, u1);
            mr1 = fminf(mr1, __uint_as_float(u0));
            mg1 = fminf(mg1, __uint_as_float(u1));
        }
        if (a0) { g_mr[ts][b * NH + i0] = mr0; g_mg[ts][b * NH + i0] = mg0; }
        if (a1) { g_mr[ts][b * NH + i1] = mr1; g_mg[ts][b * NH + i1] = mg1; }
    }
}

// Epilogue + final combine (last-block election)
__global__ void __launch_bounds__(256) k_epi(
    const float* __restrict__ recon, const float* __restrict__ gt,
    const float* __restrict__ recon_n, const float* __restrict__ gt_n,
    const float* __restrict__ obj,
    const float* __restrict__ mean, const float* __restrict__ logv,
    const float* __restrict__ vw, float* __restrict__ out)
{
    const int gid = blockIdx.x * blockDim.x + threadIdx.x;
    const int stride = gridDim.x * blockDim.x;
    const int tid = threadIdx.x;

    // a: penetr, n_pts, contact, consist, loss_o, loss_h, mse, kld
    float a[8] = {0.f,0.f,0.f,0.f,0.f,0.f,0.f,0.f};

    for (int idx = gid; idx < B_ * NO; idx += stride) {
        const int b = idx / NO;
        const int j = idx - b * NO;
        const float* ob = obj + (size_t)b * NO * 3;
        const float ox = ob[3*j], oy = ob[3*j+1], oz = ob[3*j+2];
        const unsigned br = min(min(g_okr[0][idx], g_okr[1][idx]),
                                min(g_okr[2][idx], g_okr[3][idx]));
        const unsigned bg = min(min(g_okg[0][idx], g_okg[1][idx]),
                                min(g_okg[2][idx], g_okg[3][idx]));
        const int ir = (int)(br & 1023u);
        const int ig = (int)(bg & 1023u);
        const float mp = g_mp[idx];

        const float* rb  = recon   + (size_t)b * NH * 3;
        const float* gb  = gt      + (size_t)b * NH * 3;
        const float* rnb = recon_n + (size_t)b * NH * 3;
        const float* gnb = gt_n    + (size_t)b * NH * 3;

        float dxr = ox - rb[3*ir], dyr = oy - rb[3*ir+1], dzr = oz - rb[3*ir+2];
        float d2r = dxr*dxr + dyr*dyr + dzr*dzr;
        float dotr = rnb[3*ir]*dxr + rnb[3*ir+1]*dyr + rnb[3*ir+2]*dzr;
        float o2h = sqrtf(d2r) * sgnf(dotr);
        bool interior = (-dotr) > 0.f;

        float dxg = ox - gb[3*ig], dyg = oy - gb[3*ig+1], dzg = oz - gb[3*ig+2];
        float d2g = dxg*dxg + dyg*dyg + dzg*dzg;
        float dotg = gnb[3*ig]*dxg + gnb[3*ig+1]*dyg + gnb[3*ig+2]*dzg;
        float o2h_gt = sqrtf(d2g) * sgnf(dotg);

        float d2p = fmaxf(2.f * mp, 0.f);
        bool cmap  = sqrtf(d2g) < 0.005f;
        bool rcmap = sqrtf(d2r) < 0.005f;

        a[0] += interior ? d2r : 0.f;
        a[1] += cmap ? 1.f : 0.f;
        a[2] += cmap ? d2p : 0.f;
        a[3] += (cmap && rcmap) ? 1.f : 0.f;
        bool w_dist = (o2h_gt < 0.01f) && (o2h_gt > -0.005f);
        float w = (o2h < 0.f) ? 1.5f : (w_dist ? 1.0f : 0.1f);
        a[4] += fabsf(o2h - o2h_gt) * w;
    }

    for (int j = gid; j < B_ * NH; j += stride) {
        const int i = j % NH;
        float mr = g_mr[0][j], mg = g_mg[0][j];
#pragma unroll
        for (int s = 1; s < HAND_TSEG; s++) {
            mr = fminf(mr, g_mr[s][j]);
            mg = fminf(mg, g_mg[s][j]);
        }
        float dr = sqrtf(fmaxf(2.f * mr, 0.f));
        float dg = sqrtf(fmaxf(2.f * mg, 0.f));
        a[5] += fabsf(dr - dg) * powf(vw[i], 0.4f);
    }

    for (int i = gid; i < B_ * NH * 3; i += stride) {
        float d = recon[i] - gt[i];
        a[6] += d * d;
    }
    for (int i = gid; i < B_ * Z_; i += stride) {
        float m = mean[i], lv = logv[i];
        a[7] += 1.f + lv - m * m - expf(lv);
    }

    __shared__ float red[8][8];
    __shared__ bool s_last;
    const int lane = tid & 31, warp = tid >> 5;
#pragma unroll
    for (int q = 0; q < 8; q++) {
        float v = warp_sum(a[q]);
        if (lane == 0) red[warp][q] = v;
    }
    __syncthreads();
    if (tid < 8) {
        float s = 0.f;
#pragma unroll
        for (int wi = 0; wi < 8; wi++) s += red[wi][tid];
        g_epart[blockIdx.x][tid] = s;
    }
    if (tid == 0) {
        __threadfence();
        unsigned t = atomicAdd(&g_ctr, 1u);
        s_last = (t == (unsigned)(gridDim.x - 1));
    }
    __syncthreads();

    if (s_last) {
        __threadfence();
        float p[8] = {0.f,0.f,0.f,0.f,0.f,0.f,0.f,0.f};
        for (int i = tid; i < EPI_BLOCKS; i += 256) {
#pragma unroll
            for (int q = 0; q < 8; q++) p[q] += g_epart[i][q];
        }
#pragma unroll
        for (int q = 0; q < 8; q++) {
            float v = warp_sum(p[q]);
            if (lane == 0) red[warp][q] = v;
        }
        __syncthreads();
        if (tid == 0) {
            double acc[8];
#pragma unroll
            for (int q = 0; q < 8; q++) {
                float s = 0.f;
                for (int wi = 0; wi < 8; wi++) s += red[wi][q];
                acc[q] = (double)s;
            }
            const double KLC = 0.005;
            double recon_loss = acc[6] / B_;
            double kld        = -0.5 * acc[7] / B_ * 10.0;
            double penetr     = 100.0 * acc[0] / B_;
            double npts       = acc[1];
            double contact    = 3000.0 * ((npts > 0.0) ? (acc[2] / (B_ * npts)) : 0.0);
            double consist    = -5.0 * acc[3] / (npts + 0.0001);
            double loss_o     = 30.0 * (1.0 - KLC) * acc[4] / ((double)B_ * NO);
            double loss_h     = 35.0 * (1.0 - KLC) * acc[5] / ((double)B_ * NH);
            double total = recon_loss + 0.1 * kld + 1000.0 * penetr
                         + 10.0 * contact + 10.0 * consist + (loss_h + loss_o);
            out[0] = (float)total;
            g_ctr = 0u;   // reset for next graph replay
        }
    }
}

extern "C" void kernel_launch(void* const* d_in, const int* in_sizes, int n_in,
                              void* d_out, int out_size) {
    const float* recon   = (const float*)d_in[0];
    const float* gt      = (const float*)d_in[1];
    const float* recon_n = (const float*)d_in[2];
    const float* gt_n    = (const float*)d_in[3];
    const float* obj     = (const float*)d_in[4];
    const float* mean    = (const float*)d_in[5];
    const float* logv    = (const float*)d_in[6];
    const float* vw      = (const float*)d_in[7];
    float* out = (float*)d_out;

    k_main<<<TOTAL_ITEMS, 256>>>(recon, gt, obj);
    k_epi<<<EPI_BLOCKS, 256>>>(recon, gt, recon_n, gt_n, obj, mean, logv, vw, out);
}